// round 9
// baseline (speedup 1.0000x reference)
#include <cuda_runtime.h>
#include <cuda_bf16.h>
#include <cuda_fp16.h>
#include <cstdint>
#include <math.h>

// ---------------------------------------------------------------------------
// QuantumLayer, split by resource:
//  1) setup_kernel    : 64x64 circulant generator -> HMMA B-fragment table
//  2) noise_kernel    : pure threefry/erfinv (alu-bound), writes fp16 deltas
//                       in the main kernel's exact access order (coalesced)
//  3) quantum_main    : bf16-split HMMA matmul + noise apply + L2-norm + abs
// ---------------------------------------------------------------------------

#define DTOT 4096
#define CTAS 2048          // 2 tokens per CTA

__device__ uint2 d_Bfrag[2048];        // HMMA B fragments [img][j][kk][lane]
__device__ uint2 d_noise[CTAS * 2048]; // fp16 noise deltas [blk][j][tid], 33.5MB

// ------------------------- small helpers -----------------------------------
__device__ __forceinline__ unsigned smem_u32(const void* p) {
    unsigned a;
    asm("{ .reg .u64 t; cvta.to.shared.u64 t, %1; cvt.u32.u64 %0, t; }" : "=r"(a) : "l"(p));
    return a;
}
__device__ __forceinline__ void cp_async16(void* s, const void* g) {
    asm volatile("cp.async.ca.shared.global [%0], [%1], 16;" :: "r"(smem_u32(s)), "l"(g));
}
__device__ __forceinline__ unsigned pack_bf16x2(float lo_e, float hi_e) {
    unsigned r;
    asm("cvt.rn.bf16x2.f32 %0, %1, %2;" : "=r"(r) : "f"(hi_e), "f"(lo_e));
    return r;
}
__device__ __forceinline__ void split2(float a, float b, unsigned &hi, unsigned &lo) {
    unsigned h = pack_bf16x2(a, b);
    float ha = __uint_as_float(h << 16);
    float hb = __uint_as_float(h & 0xffff0000u);
    hi = h;
    lo = pack_bf16x2(a - ha, b - hb);
}
__device__ __forceinline__ unsigned pack_f16x2(float lo_e, float hi_e) {
    unsigned r;
    asm("cvt.rn.f16x2.f32 %0, %1, %2;" : "=r"(r) : "f"(hi_e), "f"(lo_e));
    return r;
}
#define HMMA(c0,c1,c2,c3,a,b0,b1)                                              \
    asm volatile("mma.sync.aligned.m16n8k16.row.col.f32.bf16.bf16.f32 "        \
        "{%0,%1,%2,%3}, {%4,%5,%6,%7}, {%8,%9}, {%0,%1,%2,%3};"                \
        : "+f"(c0), "+f"(c1), "+f"(c2), "+f"(c3)                               \
        : "r"((a)[0]), "r"((a)[1]), "r"((a)[2]), "r"((a)[3]), "r"(b0), "r"(b1))

// ------------------------- threefry2x32 (exact) ----------------------------
__host__ __device__ __forceinline__ unsigned rotl32(unsigned x, int r) {
#if defined(__CUDA_ARCH__)
    return __funnelshift_l(x, x, r);
#else
    return (x << r) | (x >> (32 - r));
#endif
}
__host__ __device__ __forceinline__ void threefry2x32(
    unsigned k0, unsigned k1, unsigned c0, unsigned c1, unsigned &y0, unsigned &y1)
{
    unsigned ks2 = k0 ^ k1 ^ 0x1BD11BDAu;
    unsigned x0 = c0 + k0;
    unsigned x1 = c1 + k1;
#define TF_R(r) { x0 += x1; x1 = rotl32(x1, (r)); x1 ^= x0; }
    TF_R(13) TF_R(15) TF_R(26) TF_R(6)
    x0 += k1;  x1 += ks2 + 1u;
    TF_R(17) TF_R(29) TF_R(16) TF_R(24)
    x0 += ks2; x1 += k0 + 2u;
    TF_R(13) TF_R(15) TF_R(26) TF_R(6)
    x0 += k0;  x1 += k1 + 3u;
    TF_R(17) TF_R(29) TF_R(16) TF_R(24)
    x0 += k1;  x1 += ks2 + 4u;
    TF_R(13) TF_R(15) TF_R(26) TF_R(6)
    x0 += ks2; x1 += k0 + 5u;
#undef TF_R
    y0 = x0; y1 = x1;
}

__device__ __forceinline__ float erfinv_approx(float x)
{
    float w = -__logf(fmaf(-x, x, 1.0f));
    float p;
    if (w < 5.0f) {
        w = w - 2.5f;
        p = 2.81022636e-08f;
        p = fmaf(p, w, 3.43273939e-07f);
        p = fmaf(p, w, -3.5233877e-06f);
        p = fmaf(p, w, -4.39150654e-06f);
        p = fmaf(p, w, 0.00021858087f);
        p = fmaf(p, w, -0.00125372503f);
        p = fmaf(p, w, -0.00417768164f);
        p = fmaf(p, w, 0.246640727f);
        p = fmaf(p, w, 1.50140941f);
    } else {
        w = sqrtf(w) - 3.0f;
        p = -0.000200214257f;
        p = fmaf(p, w, 0.000100950558f);
        p = fmaf(p, w, 0.00134934322f);
        p = fmaf(p, w, -0.00367342844f);
        p = fmaf(p, w, 0.00573950773f);
        p = fmaf(p, w, -0.0076224613f);
        p = fmaf(p, w, 0.00943887047f);
        p = fmaf(p, w, 1.00167406f);
        p = fmaf(p, w, 2.83297682f);
    }
    return p * x;
}

// delta = 0.01 * z  (noise multiplier is 1 + delta)
__device__ __forceinline__ float noise_delta(
    unsigned ka0, unsigned ka1, unsigned ks2, unsigned j)
{
    unsigned x0 = ka0;
    unsigned x1 = j + ka1;
#define TF_R(r) { x0 += x1; x1 = rotl32(x1, (r)); x1 ^= x0; }
    TF_R(13) TF_R(15) TF_R(26) TF_R(6)
    x0 += ka1; x1 += ks2 + 1u;
    TF_R(17) TF_R(29) TF_R(16) TF_R(24)
    x0 += ks2; x1 += ka0 + 2u;
    TF_R(13) TF_R(15) TF_R(26) TF_R(6)
    x0 += ka0; x1 += ka1 + 3u;
    TF_R(17) TF_R(29) TF_R(16) TF_R(24)
    x0 += ka1; x1 += ks2 + 4u;
    TF_R(13) TF_R(15) TF_R(26) TF_R(6)
    x0 += ks2; x1 += ka0 + 5u;
#undef TF_R
    unsigned bits = x0 ^ x1;
    float v = (float)(bits >> 9);                       // exact I2F (23 bits)
    float u = fmaf(v, 2.3841858e-07f, -0.99999994f);    // jax uniform mapping
    float z = 1.41421354f * erfinv_approx(u);
    return 0.01f * z;
}

// ------------------------- noise kernel (pure PRNG, alu-bound) -------------
__global__ void __launch_bounds__(256, 5)
noise_kernel(unsigned ka0, unsigned ka1)
{
    const int tid = threadIdx.x;
    const int w   = tid >> 5;
    const int l   = tid & 31;
    const int t   = w >> 2;
    const int dg  = (w & 3) * 16 + (l >> 2);
    const int blk = blockIdx.x;
    const unsigned ks2 = ka0 ^ ka1 ^ 0x1BD11BDAu;
    const unsigned jb = (unsigned)((2 * blk + t) * DTOT) + (unsigned)dg;
    uint2* ob = d_noise + blk * 2048 + tid;

#pragma unroll
    for (int j = 0; j < 8; j++) {
        const unsigned b = jb + (unsigned)(j * 8 + (l & 3) * 2) * 64u;
        float d0 = noise_delta(ka0, ka1, ks2, b);
        float d1 = noise_delta(ka0, ka1, ks2, b + 64u);
        float d2 = noise_delta(ka0, ka1, ks2, b + 8u);
        float d3 = noise_delta(ka0, ka1, ks2, b + 72u);
        ob[j * 256] = make_uint2(pack_f16x2(d0, d1), pack_f16x2(d2, d3));
    }
}

// ------------------------- setup: generator + B-fragment table -------------
__global__ void setup_kernel(const float* __restrict__ rx,
                             const float* __restrict__ ry,
                             const float* __restrict__ rz)
{
    __shared__ float c64[64], s64[64];
    __shared__ float cthx[32], cthy[32], cthz[32], sthz[32];
    __shared__ float cx[64], cy[64], cz[64], hh[64], gg[64];
    const int tid = threadIdx.x;   // 0..255
    const int m = tid;

    if (m < 64) {
        c64[m] = cospif((float)m / 32.0f);
        s64[m] = sinpif((float)m / 32.0f);
    }
    if (m < 32) {
        float sx = 0.0f, sy = 0.0f, sz = 0.0f;
        for (int j = 0; j < 16; j++) {
            sx += rx[m * 16 + j];
            sy += ry[m * 16 + j];
            sz += rz[m * 16 + j];
        }
        cthx[m] = cosf(0.5f * sx);
        cthy[m] = cosf(0.5f * sy);
        cthz[m] = cosf(0.5f * sz);
        sthz[m] = sinf(0.5f * sz);
    }
    __syncthreads();

    if (m < 64) {
        float ax = 0.0f, ay = 0.0f, az = 0.0f;
        for (int k = 0; k < 32; k++) {
            int n0 = (2 * k * m) & 63;
            int n1 = ((2 * k + 1) * m) & 63;
            float cc = c64[n0] + c64[n1];
            ax = fmaf(cthx[k], cc, ax);
            ay = fmaf(cthy[k], cc, ay);
            az = fmaf(cthz[k], cc, fmaf(sthz[k], s64[n0] - s64[n1], az));
        }
        cx[m] = ax * (1.0f / 64.0f);
        cy[m] = ay * (1.0f / 64.0f);
        cz[m] = az * (1.0f / 64.0f);
    }
    __syncthreads();

    if (m < 64) {
        float acc = 0.0f;
        for (int s = 0; s < 64; s++) acc = fmaf(cy[s], cx[(m - s) & 63], acc);
        hh[m] = acc;
    }
    __syncthreads();

    if (m < 64) {
        float g = 0.0f;
        for (int s = 0; s < 64; s++) g = fmaf(cz[s], hh[(m - s) & 63], g);
        gg[m] = g;
    }
    __syncthreads();

    // B = G^T fragments for mma.m16n8k16.row.col: B[k=p][n=q] = g[(q-p)&63]
    for (int e = tid; e < 2048; e += 256) {
        int lane = e & 31;
        int kk   = (e >> 5) & 3;
        int j    = (e >> 7) & 7;
        int img  = e >> 10;
        int p0 = kk * 16 + (lane & 3) * 2;
        int q  = j * 8 + (lane >> 2);
        float v0 = gg[(q - p0) & 63];
        float v1 = gg[(q - p0 - 1) & 63];
        float v2 = gg[(q - p0 - 8) & 63];
        float v3 = gg[(q - p0 - 9) & 63];
        unsigned h0, l0, h1, l1;
        split2(v0, v1, h0, l0);
        split2(v2, v3, h1, l1);
        d_Bfrag[e] = (img == 0) ? make_uint2(h0, h1) : make_uint2(l0, l1);
    }
}

// ------------------------- main kernel -------------------------------------
__global__ void __launch_bounds__(256, 4)
quantum_main(const float* __restrict__ x, float* __restrict__ out)
{
    __shared__ __align__(16) uint2 Bf[2048];   // [img][j][kk][lane], 16KB
    __shared__ float red[8];

    const int tid = threadIdx.x;
    const int w   = tid >> 5;
    const int l   = tid & 31;
    const int t   = w >> 2;                   // token within CTA pair
    const int dg  = (w & 3) * 16 + (l >> 2);  // this thread's base d (row)
    const int blk = blockIdx.x;

    // --- async copy of B fragments (64B per thread) ---
#pragma unroll
    for (int i = 0; i < 4; i++)
        cp_async16(&Bf[tid * 8 + i * 2], &d_Bfrag[tid * 8 + i * 2]);
    asm volatile("cp.async.commit_group;");

    // --- A fragments straight from gmem (each byte read once, 4-sector LDGs) ---
    const float* xb = x + (size_t)(2 * blk + t) * DTOT + dg;
    unsigned ahi[4][4], alo[4][4];
#pragma unroll
    for (int kk = 0; kk < 4; kk++) {
        const float* xp = xb + (kk * 16 + (l & 3) * 2) * 64;
        float v00 = xp[0],        v01 = xp[64];
        float v10 = xp[8],        v11 = xp[64 + 8];
        float v20 = xp[512],      v21 = xp[576];
        float v30 = xp[512 + 8],  v31 = xp[576 + 8];
        split2(v00, v01, ahi[kk][0], alo[kk][0]);
        split2(v10, v11, ahi[kk][1], alo[kk][1]);
        split2(v20, v21, ahi[kk][2], alo[kk][2]);
        split2(v30, v31, ahi[kk][3], alo[kk][3]);
    }

    // --- prefetch this thread's 8 noise words (L2-resident, MLP=8) ---
    uint2 nd[8];
#pragma unroll
    for (int j = 0; j < 8; j++)
        nd[j] = __ldg(&d_noise[blk * 2048 + j * 256 + tid]);

    asm volatile("cp.async.wait_group 0;");
    __syncthreads();

    // --- 8 n-tiles: 12 HMMAs (3-term bf16 split); noisy values -> L2 (stcg) ---
    float s = 0.0f;
    float* o = out + (size_t)(2 * blk + t) * DTOT + dg;
#pragma unroll
    for (int j = 0; j < 8; j++) {
        float c0 = 0.f, c1 = 0.f, c2 = 0.f, c3 = 0.f;
#pragma unroll
        for (int kk = 0; kk < 4; kk++) {
            uint2 bh = Bf[(j * 4 + kk) * 32 + l];
            uint2 bl = Bf[1024 + (j * 4 + kk) * 32 + l];
            HMMA(c0, c1, c2, c3, ahi[kk], bh.x, bh.y);
            HMMA(c0, c1, c2, c3, alo[kk], bh.x, bh.y);
            HMMA(c0, c1, c2, c3, ahi[kk], bl.x, bl.y);
        }
        float2 f01 = __half22float2(*reinterpret_cast<const __half2*>(&nd[j].x));
        float2 f23 = __half22float2(*reinterpret_cast<const __half2*>(&nd[j].y));
        float w0 = fmaf(c0, f01.x, c0);
        float w1 = fmaf(c1, f01.y, c1);
        float w2 = fmaf(c2, f23.x, c2);
        float w3 = fmaf(c3, f23.y, c3);
        s = fmaf(w0, w0, fmaf(w1, w1, fmaf(w2, w2, fmaf(w3, w3, s))));
        const unsigned qe = (unsigned)(j * 8 + (l & 3) * 2);
        float* oj = o + qe * 64;
        __stcg(oj,      w0);
        __stcg(oj + 64, w1);
        __stcg(oj + 8,  w2);
        __stcg(oj + 72, w3);
    }

    // --- per-token norm: warp reduce + 4 warps per token via smem ---
#pragma unroll
    for (int off = 16; off > 0; off >>= 1)
        s += __shfl_xor_sync(0xffffffffu, s, off);
    if (l == 0) red[w] = s;
    __syncthreads();
    const float S = red[t * 4] + red[t * 4 + 1] + red[t * 4 + 2] + red[t * 4 + 3];
    const float inv = __fdividef(1.0f, sqrtf(S) + 1e-8f);

    // --- read back own values from L2, finalize |w| * inv ---
#pragma unroll
    for (int j = 0; j < 8; j++) {
        const int qe = j * 8 + (l & 3) * 2;
        float* oj = o + qe * 64;
        float w0 = __ldcg(oj);
        float w1 = __ldcg(oj + 64);
        float w2 = __ldcg(oj + 8);
        float w3 = __ldcg(oj + 72);
        __stcg(oj,      fabsf(w0) * inv);
        __stcg(oj + 64, fabsf(w1) * inv);
        __stcg(oj + 8,  fabsf(w2) * inv);
        __stcg(oj + 72, fabsf(w3) * inv);
    }
}

// ------------------------- launch ------------------------------------------
extern "C" void kernel_launch(void* const* d_in, const int* in_sizes, int n_in,
                              void* d_out, int out_size)
{
    const float* x  = (const float*)d_in[0];
    const float* rx = (const float*)d_in[1];
    const float* ry = (const float*)d_in[2];
    const float* rz = (const float*)d_in[3];
    float* out = (float*)d_out;

    unsigned ka0, ka1;
    threefry2x32(0u, 42u, 0u, 0u, ka0, ka1);

    setup_kernel<<<1, 256>>>(rx, ry, rz);
    noise_kernel<<<CTAS, 256>>>(ka0, ka1);
    quantum_main<<<CTAS, 256>>>(x, out);
}

// round 10
// speedup vs baseline: 1.1357x; 1.1357x over previous
#include <cuda_runtime.h>
#include <cuda_bf16.h>
#include <cstdint>
#include <math.h>

// ---------------------------------------------------------------------------
// QuantumLayer: three FFT-diagonal rotations = ONE real 64x64 circulant along
// the qubit axis -> bf16-split mma.sync HMMA (tensor pipe). Amplitude noise
// (threefry2x32, JAX partitionable) + per-token L2 norm + abs, fused.
// 1 token per 128-thread CTA (8 CTAs/SM) to minimize tail/startup bubbles.
// ---------------------------------------------------------------------------

#define DTOT 4096
#define CTAS 4096          // 1 token per CTA

// B-fragment table, fragment-register order: [img(hi,lo)][j(8)][kk(4)][lane(32)]
__device__ uint2 d_Bfrag[2048];

// ------------------------- small helpers -----------------------------------
__device__ __forceinline__ unsigned smem_u32(const void* p) {
    unsigned a;
    asm("{ .reg .u64 t; cvta.to.shared.u64 t, %1; cvt.u32.u64 %0, t; }" : "=r"(a) : "l"(p));
    return a;
}
__device__ __forceinline__ void cp_async16(void* s, const void* g) {
    asm volatile("cp.async.ca.shared.global [%0], [%1], 16;" :: "r"(smem_u32(s)), "l"(g));
}
// pack two f32 -> bf16x2, first arg in LOW half
__device__ __forceinline__ unsigned pack_bf16x2(float lo_e, float hi_e) {
    unsigned r;
    asm("cvt.rn.bf16x2.f32 %0, %1, %2;" : "=r"(r) : "f"(hi_e), "f"(lo_e));
    return r;
}
__device__ __forceinline__ void split2(float a, float b, unsigned &hi, unsigned &lo) {
    unsigned h = pack_bf16x2(a, b);
    float ha = __uint_as_float(h << 16);
    float hb = __uint_as_float(h & 0xffff0000u);
    hi = h;
    lo = pack_bf16x2(a - ha, b - hb);
}
#define HMMA(c0,c1,c2,c3,a,b0,b1)                                              \
    asm volatile("mma.sync.aligned.m16n8k16.row.col.f32.bf16.bf16.f32 "        \
        "{%0,%1,%2,%3}, {%4,%5,%6,%7}, {%8,%9}, {%0,%1,%2,%3};"                \
        : "+f"(c0), "+f"(c1), "+f"(c2), "+f"(c3)                               \
        : "r"((a)[0]), "r"((a)[1]), "r"((a)[2]), "r"((a)[3]), "r"(b0), "r"(b1))

// ------------------------- threefry2x32 (exact) ----------------------------
__host__ __device__ __forceinline__ unsigned rotl32(unsigned x, int r) {
#if defined(__CUDA_ARCH__)
    return __funnelshift_l(x, x, r);
#else
    return (x << r) | (x >> (32 - r));
#endif
}
__host__ __device__ __forceinline__ void threefry2x32(
    unsigned k0, unsigned k1, unsigned c0, unsigned c1, unsigned &y0, unsigned &y1)
{
    unsigned ks2 = k0 ^ k1 ^ 0x1BD11BDAu;
    unsigned x0 = c0 + k0;
    unsigned x1 = c1 + k1;
#define TF_R(r) { x0 += x1; x1 = rotl32(x1, (r)); x1 ^= x0; }
    TF_R(13) TF_R(15) TF_R(26) TF_R(6)
    x0 += k1;  x1 += ks2 + 1u;
    TF_R(17) TF_R(29) TF_R(16) TF_R(24)
    x0 += ks2; x1 += k0 + 2u;
    TF_R(13) TF_R(15) TF_R(26) TF_R(6)
    x0 += k0;  x1 += k1 + 3u;
    TF_R(17) TF_R(29) TF_R(16) TF_R(24)
    x0 += k1;  x1 += ks2 + 4u;
    TF_R(13) TF_R(15) TF_R(26) TF_R(6)
    x0 += ks2; x1 += k0 + 5u;
#undef TF_R
    y0 = x0; y1 = x1;
}

__device__ __forceinline__ float erfinv_approx(float x)
{
    float w = -__logf(fmaf(-x, x, 1.0f));
    float p;
    if (w < 5.0f) {
        w = w - 2.5f;
        p = 2.81022636e-08f;
        p = fmaf(p, w, 3.43273939e-07f);
        p = fmaf(p, w, -3.5233877e-06f);
        p = fmaf(p, w, -4.39150654e-06f);
        p = fmaf(p, w, 0.00021858087f);
        p = fmaf(p, w, -0.00125372503f);
        p = fmaf(p, w, -0.00417768164f);
        p = fmaf(p, w, 0.246640727f);
        p = fmaf(p, w, 1.50140941f);
    } else {
        w = sqrtf(w) - 3.0f;
        p = -0.000200214257f;
        p = fmaf(p, w, 0.000100950558f);
        p = fmaf(p, w, 0.00134934322f);
        p = fmaf(p, w, -0.00367342844f);
        p = fmaf(p, w, 0.00573950773f);
        p = fmaf(p, w, -0.0076224613f);
        p = fmaf(p, w, 0.00943887047f);
        p = fmaf(p, w, 1.00167406f);
        p = fmaf(p, w, 2.83297682f);
    }
    return p * x;
}
__device__ __forceinline__ float noise_mult(
    unsigned k0, unsigned k1, unsigned ks2, unsigned j)
{
    unsigned x0 = k0;
    unsigned x1 = j + k1;
#define TF_R(r) { x0 += x1; x1 = rotl32(x1, (r)); x1 ^= x0; }
    TF_R(13) TF_R(15) TF_R(26) TF_R(6)
    x0 += k1;  x1 += ks2 + 1u;
    TF_R(17) TF_R(29) TF_R(16) TF_R(24)
    x0 += ks2; x1 += k0 + 2u;
    TF_R(13) TF_R(15) TF_R(26) TF_R(6)
    x0 += k0;  x1 += k1 + 3u;
    TF_R(17) TF_R(29) TF_R(16) TF_R(24)
    x0 += k1;  x1 += ks2 + 4u;
    TF_R(13) TF_R(15) TF_R(26) TF_R(6)
    x0 += ks2; x1 += k0 + 5u;
#undef TF_R
    unsigned bits = x0 ^ x1;
    float v = (float)(bits >> 9);                       // exact I2F (23 bits)
    float u = fmaf(v, 2.3841858e-07f, -0.99999994f);    // jax uniform mapping
    float z = 1.41421354f * erfinv_approx(u);
    return fmaf(z, 0.01f, 1.0f);
}

// ------------------------- setup: generator + B-fragment table -------------
__global__ void setup_kernel(const float* __restrict__ rx,
                             const float* __restrict__ ry,
                             const float* __restrict__ rz)
{
    __shared__ float c64[64], s64[64];
    __shared__ float cthx[32], cthy[32], cthz[32], sthz[32];
    __shared__ float cx[64], cy[64], cz[64], hh[64], gg[64];
    const int tid = threadIdx.x;   // 0..255
    const int m = tid;

    if (m < 64) {
        c64[m] = cospif((float)m / 32.0f);
        s64[m] = sinpif((float)m / 32.0f);
    }
    if (m < 32) {
        float sx = 0.0f, sy = 0.0f, sz = 0.0f;
        for (int j = 0; j < 16; j++) {
            sx += rx[m * 16 + j];
            sy += ry[m * 16 + j];
            sz += rz[m * 16 + j];
        }
        cthx[m] = cosf(0.5f * sx);
        cthy[m] = cosf(0.5f * sy);
        cthz[m] = cosf(0.5f * sz);
        sthz[m] = sinf(0.5f * sz);
    }
    __syncthreads();

    if (m < 64) {
        float ax = 0.0f, ay = 0.0f, az = 0.0f;
        for (int k = 0; k < 32; k++) {
            int n0 = (2 * k * m) & 63;
            int n1 = ((2 * k + 1) * m) & 63;
            float cc = c64[n0] + c64[n1];
            ax = fmaf(cthx[k], cc, ax);
            ay = fmaf(cthy[k], cc, ay);
            az = fmaf(cthz[k], cc, fmaf(sthz[k], s64[n0] - s64[n1], az));
        }
        cx[m] = ax * (1.0f / 64.0f);
        cy[m] = ay * (1.0f / 64.0f);
        cz[m] = az * (1.0f / 64.0f);
    }
    __syncthreads();

    if (m < 64) {
        float acc = 0.0f;
        for (int s = 0; s < 64; s++) acc = fmaf(cy[s], cx[(m - s) & 63], acc);
        hh[m] = acc;
    }
    __syncthreads();

    if (m < 64) {
        float g = 0.0f;
        for (int s = 0; s < 64; s++) g = fmaf(cz[s], hh[(m - s) & 63], g);
        gg[m] = g;
    }
    __syncthreads();

    // B = G^T fragments for mma.m16n8k16.row.col: B[k=p][n=q] = g[(q-p)&63]
    for (int e = tid; e < 2048; e += 256) {
        int lane = e & 31;
        int kk   = (e >> 5) & 3;
        int j    = (e >> 7) & 7;
        int img  = e >> 10;
        int p0 = kk * 16 + (lane & 3) * 2;
        int q  = j * 8 + (lane >> 2);
        float v0 = gg[(q - p0) & 63];
        float v1 = gg[(q - p0 - 1) & 63];
        float v2 = gg[(q - p0 - 8) & 63];
        float v3 = gg[(q - p0 - 9) & 63];
        unsigned h0, l0, h1, l1;
        split2(v0, v1, h0, l0);
        split2(v2, v3, h1, l1);
        d_Bfrag[e] = (img == 0) ? make_uint2(h0, h1) : make_uint2(l0, l1);
    }
}

// ------------------------- main kernel: 1 token / 128 threads ---------------
__global__ void __launch_bounds__(128, 8)
quantum_main(const float* __restrict__ x, float* __restrict__ out,
             unsigned ka0, unsigned ka1)
{
    __shared__ __align__(16) uint2 Bf[2048];   // [img][j][kk][lane], 16KB
    __shared__ float red[4];

    const int tid = threadIdx.x;
    const int w   = tid >> 5;                 // 0..3 : m16 slab
    const int l   = tid & 31;
    const int dg  = w * 16 + (l >> 2);        // this thread's base d (row)
    const int blk = blockIdx.x;               // token
    const unsigned ks2 = ka0 ^ ka1 ^ 0x1BD11BDAu;

    // --- async copy of B fragments (128B per thread) ---
#pragma unroll
    for (int i = 0; i < 8; i++)
        cp_async16(&Bf[tid * 16 + i * 2], &d_Bfrag[tid * 16 + i * 2]);
    asm volatile("cp.async.commit_group;");

    // --- A fragments straight from gmem (each byte read once, 4-sector LDGs) ---
    const float* xb = x + (size_t)blk * DTOT + dg;
    unsigned ahi[4][4], alo[4][4];
#pragma unroll
    for (int kk = 0; kk < 4; kk++) {
        const float* xp = xb + (kk * 16 + (l & 3) * 2) * 64;
        float v00 = xp[0],        v01 = xp[64];
        float v10 = xp[8],        v11 = xp[64 + 8];
        float v20 = xp[512],      v21 = xp[576];
        float v30 = xp[512 + 8],  v31 = xp[576 + 8];
        split2(v00, v01, ahi[kk][0], alo[kk][0]);
        split2(v10, v11, ahi[kk][1], alo[kk][1]);
        split2(v20, v21, ahi[kk][2], alo[kk][2]);
        split2(v30, v31, ahi[kk][3], alo[kk][3]);
    }

    asm volatile("cp.async.wait_group 0;");
    __syncthreads();

    // --- 8 n-tiles: 12 HMMAs (3-term bf16 split); noisy values -> L2 (stcg) ---
    float s = 0.0f;
    const unsigned jb = (unsigned)(blk * DTOT) + (unsigned)dg;
    float* o = out + (size_t)blk * DTOT + dg;
#pragma unroll
    for (int j = 0; j < 8; j++) {
        float c0 = 0.f, c1 = 0.f, c2 = 0.f, c3 = 0.f;
#pragma unroll
        for (int kk = 0; kk < 4; kk++) {
            uint2 bh = Bf[(j * 4 + kk) * 32 + l];
            uint2 bl = Bf[1024 + (j * 4 + kk) * 32 + l];
            HMMA(c0, c1, c2, c3, ahi[kk], bh.x, bh.y);
            HMMA(c0, c1, c2, c3, alo[kk], bh.x, bh.y);
            HMMA(c0, c1, c2, c3, ahi[kk], bl.x, bl.y);
        }
        const unsigned qe = (unsigned)(j * 8 + (l & 3) * 2);
        float n0 = noise_mult(ka0, ka1, ks2, jb + qe * 64u);
        float n1 = noise_mult(ka0, ka1, ks2, jb + qe * 64u + 64u);
        float n2 = noise_mult(ka0, ka1, ks2, jb + qe * 64u + 8u);
        float n3 = noise_mult(ka0, ka1, ks2, jb + qe * 64u + 72u);
        float w0 = c0 * n0, w1 = c1 * n1, w2 = c2 * n2, w3 = c3 * n3;
        s = fmaf(w0, w0, fmaf(w1, w1, fmaf(w2, w2, fmaf(w3, w3, s))));
        float* oj = o + qe * 64;
        __stcg(oj,      w0);
        __stcg(oj + 64, w1);
        __stcg(oj + 8,  w2);
        __stcg(oj + 72, w3);
    }

    // --- per-token norm: warp reduce + 4 warps via smem ---
#pragma unroll
    for (int off = 16; off > 0; off >>= 1)
        s += __shfl_xor_sync(0xffffffffu, s, off);
    if (l == 0) red[w] = s;
    __syncthreads();
    const float S = red[0] + red[1] + red[2] + red[3];
    const float inv = __fdividef(1.0f, sqrtf(S) + 1e-8f);

    // --- read back own values from L2, finalize |w| * inv ---
#pragma unroll
    for (int j = 0; j < 8; j++) {
        const int qe = j * 8 + (l & 3) * 2;
        float* oj = o + qe * 64;
        float w0 = __ldcg(oj);
        float w1 = __ldcg(oj + 64);
        float w2 = __ldcg(oj + 8);
        float w3 = __ldcg(oj + 72);
        __stcg(oj,      fabsf(w0) * inv);
        __stcg(oj + 64, fabsf(w1) * inv);
        __stcg(oj + 8,  fabsf(w2) * inv);
        __stcg(oj + 72, fabsf(w3) * inv);
    }
}

// ------------------------- launch ------------------------------------------
extern "C" void kernel_launch(void* const* d_in, const int* in_sizes, int n_in,
                              void* d_out, int out_size)
{
    const float* x  = (const float*)d_in[0];
    const float* rx = (const float*)d_in[1];
    const float* ry = (const float*)d_in[2];
    const float* rz = (const float*)d_in[3];
    float* out = (float*)d_out;

    unsigned ka0, ka1;
    threefry2x32(0u, 42u, 0u, 0u, ka0, ka1);

    setup_kernel<<<1, 256>>>(rx, ry, rz);
    quantum_main<<<CTAS, 128>>>(x, out, ka0, ka1);
}

// round 11
// speedup vs baseline: 1.2364x; 1.0887x over previous
#include <cuda_runtime.h>
#include <cuda_bf16.h>
#include <cstdint>
#include <math.h>

// ---------------------------------------------------------------------------
// QuantumLayer: three FFT-diagonal rotations = ONE real 64x64 circulant along
// the qubit axis -> bf16-split mma.sync HMMA (tensor pipe). Amplitude noise
// (threefry2x32, JAX partitionable) + per-token L2 norm + abs, fused.
// PERSISTENT: one wave of 592 CTAs; each grid-strides over token pairs, the
// B-fragment smem tile loaded once. Epilogue staged in thread-private smem.
// ---------------------------------------------------------------------------

#define DTOT   4096
#define NPAIR  2048        // 2 tokens per pair
#define PGRID  592         // 148 SMs x 4 CTAs: exactly one wave

// B-fragment table, fragment-register order: [img(hi,lo)][j(8)][kk(4)][lane(32)]
__device__ uint2 d_Bfrag[2048];

// ------------------------- small helpers -----------------------------------
__device__ __forceinline__ unsigned smem_u32(const void* p) {
    unsigned a;
    asm("{ .reg .u64 t; cvta.to.shared.u64 t, %1; cvt.u32.u64 %0, t; }" : "=r"(a) : "l"(p));
    return a;
}
__device__ __forceinline__ void cp_async16(void* s, const void* g) {
    asm volatile("cp.async.ca.shared.global [%0], [%1], 16;" :: "r"(smem_u32(s)), "l"(g));
}
// pack two f32 -> bf16x2, first arg in LOW half
__device__ __forceinline__ unsigned pack_bf16x2(float lo_e, float hi_e) {
    unsigned r;
    asm("cvt.rn.bf16x2.f32 %0, %1, %2;" : "=r"(r) : "f"(hi_e), "f"(lo_e));
    return r;
}
__device__ __forceinline__ void split2(float a, float b, unsigned &hi, unsigned &lo) {
    unsigned h = pack_bf16x2(a, b);
    float ha = __uint_as_float(h << 16);
    float hb = __uint_as_float(h & 0xffff0000u);
    hi = h;
    lo = pack_bf16x2(a - ha, b - hb);
}
#define HMMA(c0,c1,c2,c3,a,b0,b1)                                              \
    asm volatile("mma.sync.aligned.m16n8k16.row.col.f32.bf16.bf16.f32 "        \
        "{%0,%1,%2,%3}, {%4,%5,%6,%7}, {%8,%9}, {%0,%1,%2,%3};"                \
        : "+f"(c0), "+f"(c1), "+f"(c2), "+f"(c3)                               \
        : "r"((a)[0]), "r"((a)[1]), "r"((a)[2]), "r"((a)[3]), "r"(b0), "r"(b1))

// ------------------------- threefry2x32 (exact) ----------------------------
__host__ __device__ __forceinline__ unsigned rotl32(unsigned x, int r) {
#if defined(__CUDA_ARCH__)
    return __funnelshift_l(x, x, r);
#else
    return (x << r) | (x >> (32 - r));
#endif
}
__host__ __device__ __forceinline__ void threefry2x32(
    unsigned k0, unsigned k1, unsigned c0, unsigned c1, unsigned &y0, unsigned &y1)
{
    unsigned ks2 = k0 ^ k1 ^ 0x1BD11BDAu;
    unsigned x0 = c0 + k0;
    unsigned x1 = c1 + k1;
#define TF_R(r) { x0 += x1; x1 = rotl32(x1, (r)); x1 ^= x0; }
    TF_R(13) TF_R(15) TF_R(26) TF_R(6)
    x0 += k1;  x1 += ks2 + 1u;
    TF_R(17) TF_R(29) TF_R(16) TF_R(24)
    x0 += ks2; x1 += k0 + 2u;
    TF_R(13) TF_R(15) TF_R(26) TF_R(6)
    x0 += k0;  x1 += k1 + 3u;
    TF_R(17) TF_R(29) TF_R(16) TF_R(24)
    x0 += k1;  x1 += ks2 + 4u;
    TF_R(13) TF_R(15) TF_R(26) TF_R(6)
    x0 += ks2; x1 += k0 + 5u;
#undef TF_R
    y0 = x0; y1 = x1;
}

__device__ __forceinline__ float erfinv_approx(float x)
{
    float w = -__logf(fmaf(-x, x, 1.0f));
    float p;
    if (w < 5.0f) {
        w = w - 2.5f;
        p = 2.81022636e-08f;
        p = fmaf(p, w, 3.43273939e-07f);
        p = fmaf(p, w, -3.5233877e-06f);
        p = fmaf(p, w, -4.39150654e-06f);
        p = fmaf(p, w, 0.00021858087f);
        p = fmaf(p, w, -0.00125372503f);
        p = fmaf(p, w, -0.00417768164f);
        p = fmaf(p, w, 0.246640727f);
        p = fmaf(p, w, 1.50140941f);
    } else {
        w = sqrtf(w) - 3.0f;
        p = -0.000200214257f;
        p = fmaf(p, w, 0.000100950558f);
        p = fmaf(p, w, 0.00134934322f);
        p = fmaf(p, w, -0.00367342844f);
        p = fmaf(p, w, 0.00573950773f);
        p = fmaf(p, w, -0.0076224613f);
        p = fmaf(p, w, 0.00943887047f);
        p = fmaf(p, w, 1.00167406f);
        p = fmaf(p, w, 2.83297682f);
    }
    return p * x;
}
__device__ __forceinline__ float noise_mult(
    unsigned k0, unsigned k1, unsigned ks2, unsigned j)
{
    unsigned x0 = k0;
    unsigned x1 = j + k1;
#define TF_R(r) { x0 += x1; x1 = rotl32(x1, (r)); x1 ^= x0; }
    TF_R(13) TF_R(15) TF_R(26) TF_R(6)
    x0 += k1;  x1 += ks2 + 1u;
    TF_R(17) TF_R(29) TF_R(16) TF_R(24)
    x0 += ks2; x1 += k0 + 2u;
    TF_R(13) TF_R(15) TF_R(26) TF_R(6)
    x0 += k0;  x1 += k1 + 3u;
    TF_R(17) TF_R(29) TF_R(16) TF_R(24)
    x0 += k1;  x1 += ks2 + 4u;
    TF_R(13) TF_R(15) TF_R(26) TF_R(6)
    x0 += ks2; x1 += k0 + 5u;
#undef TF_R
    unsigned bits = x0 ^ x1;
    float v = (float)(bits >> 9);                       // exact I2F (23 bits)
    float u = fmaf(v, 2.3841858e-07f, -0.99999994f);    // jax uniform mapping
    float z = 1.41421354f * erfinv_approx(u);
    return fmaf(z, 0.01f, 1.0f);
}

// ------------------------- setup: generator + B-fragment table -------------
__global__ void setup_kernel(const float* __restrict__ rx,
                             const float* __restrict__ ry,
                             const float* __restrict__ rz)
{
    __shared__ float c64[64], s64[64];
    __shared__ float cthx[32], cthy[32], cthz[32], sthz[32];
    __shared__ float cx[64], cy[64], cz[64], hh[64], gg[64];
    const int tid = threadIdx.x;   // 0..255
    const int m = tid;

    if (m < 64) {
        c64[m] = cospif((float)m / 32.0f);
        s64[m] = sinpif((float)m / 32.0f);
    }
    if (m < 32) {
        float sx = 0.0f, sy = 0.0f, sz = 0.0f;
        for (int j = 0; j < 16; j++) {
            sx += rx[m * 16 + j];
            sy += ry[m * 16 + j];
            sz += rz[m * 16 + j];
        }
        cthx[m] = cosf(0.5f * sx);
        cthy[m] = cosf(0.5f * sy);
        cthz[m] = cosf(0.5f * sz);
        sthz[m] = sinf(0.5f * sz);
    }
    __syncthreads();

    if (m < 64) {
        float ax = 0.0f, ay = 0.0f, az = 0.0f;
        for (int k = 0; k < 32; k++) {
            int n0 = (2 * k * m) & 63;
            int n1 = ((2 * k + 1) * m) & 63;
            float cc = c64[n0] + c64[n1];
            ax = fmaf(cthx[k], cc, ax);
            ay = fmaf(cthy[k], cc, ay);
            az = fmaf(cthz[k], cc, fmaf(sthz[k], s64[n0] - s64[n1], az));
        }
        cx[m] = ax * (1.0f / 64.0f);
        cy[m] = ay * (1.0f / 64.0f);
        cz[m] = az * (1.0f / 64.0f);
    }
    __syncthreads();

    if (m < 64) {
        float acc = 0.0f;
        for (int s = 0; s < 64; s++) acc = fmaf(cy[s], cx[(m - s) & 63], acc);
        hh[m] = acc;
    }
    __syncthreads();

    if (m < 64) {
        float g = 0.0f;
        for (int s = 0; s < 64; s++) g = fmaf(cz[s], hh[(m - s) & 63], g);
        gg[m] = g;
    }
    __syncthreads();

    // B = G^T fragments for mma.m16n8k16.row.col: B[k=p][n=q] = g[(q-p)&63]
    for (int e = tid; e < 2048; e += 256) {
        int lane = e & 31;
        int kk   = (e >> 5) & 3;
        int j    = (e >> 7) & 7;
        int img  = e >> 10;
        int p0 = kk * 16 + (lane & 3) * 2;
        int q  = j * 8 + (lane >> 2);
        float v0 = gg[(q - p0) & 63];
        float v1 = gg[(q - p0 - 1) & 63];
        float v2 = gg[(q - p0 - 8) & 63];
        float v3 = gg[(q - p0 - 9) & 63];
        unsigned h0, l0, h1, l1;
        split2(v0, v1, h0, l0);
        split2(v2, v3, h1, l1);
        d_Bfrag[e] = (img == 0) ? make_uint2(h0, h1) : make_uint2(l0, l1);
    }
}

// ------------------------- main kernel: persistent, 2 tokens / iter --------
__global__ void __launch_bounds__(256, 4)
quantum_main(const float* __restrict__ x, float* __restrict__ out,
             unsigned ka0, unsigned ka1)
{
    __shared__ __align__(16) uint2  Bf[2048];   // [img][j][kk][lane], 16KB
    __shared__ __align__(16) float4 ws4[2048];  // staging: [j(8)][tid(256)], 32KB
    __shared__ float red[8];

    const int tid = threadIdx.x;
    const int w   = tid >> 5;
    const int l   = tid & 31;
    const int t   = w >> 2;                   // token within pair
    const int dg  = (w & 3) * 16 + (l >> 2);  // this thread's base d (row)
    const unsigned ks2 = ka0 ^ ka1 ^ 0x1BD11BDAu;

    // --- B fragments: once per CTA ---
#pragma unroll
    for (int i = 0; i < 4; i++)
        cp_async16(&Bf[tid * 8 + i * 2], &d_Bfrag[tid * 8 + i * 2]);
    asm volatile("cp.async.commit_group;");
    asm volatile("cp.async.wait_group 0;");

    for (int pair = blockIdx.x; pair < NPAIR; pair += PGRID) {
        const int tok = 2 * pair + t;

        // --- A fragments straight from gmem (each byte read once) ---
        const float* xb = x + (size_t)tok * DTOT + dg;
        unsigned ahi[4][4], alo[4][4];
#pragma unroll
        for (int kk = 0; kk < 4; kk++) {
            const float* xp = xb + (kk * 16 + (l & 3) * 2) * 64;
            float v00 = xp[0],        v01 = xp[64];
            float v10 = xp[8],        v11 = xp[64 + 8];
            float v20 = xp[512],      v21 = xp[576];
            float v30 = xp[512 + 8],  v31 = xp[576 + 8];
            split2(v00, v01, ahi[kk][0], alo[kk][0]);
            split2(v10, v11, ahi[kk][1], alo[kk][1]);
            split2(v20, v21, ahi[kk][2], alo[kk][2]);
            split2(v30, v31, ahi[kk][3], alo[kk][3]);
        }

        __syncthreads();   // Bf ready (iter 0); red[] reads of prev iter done

        // --- 8 n-tiles: 12 HMMAs (3-term bf16 split); w -> private smem ---
        float s = 0.0f;
        const unsigned jb = (unsigned)(tok * DTOT) + (unsigned)dg;
#pragma unroll
        for (int j = 0; j < 8; j++) {
            float c0 = 0.f, c1 = 0.f, c2 = 0.f, c3 = 0.f;
#pragma unroll
            for (int kk = 0; kk < 4; kk++) {
                uint2 bh = Bf[(j * 4 + kk) * 32 + l];
                uint2 bl = Bf[1024 + (j * 4 + kk) * 32 + l];
                HMMA(c0, c1, c2, c3, ahi[kk], bh.x, bh.y);
                HMMA(c0, c1, c2, c3, alo[kk], bh.x, bh.y);
                HMMA(c0, c1, c2, c3, ahi[kk], bl.x, bl.y);
            }
            const unsigned qe = (unsigned)(j * 8 + (l & 3) * 2);
            float n0 = noise_mult(ka0, ka1, ks2, jb + qe * 64u);
            float n1 = noise_mult(ka0, ka1, ks2, jb + qe * 64u + 64u);
            float n2 = noise_mult(ka0, ka1, ks2, jb + qe * 64u + 8u);
            float n3 = noise_mult(ka0, ka1, ks2, jb + qe * 64u + 72u);
            float w0 = c0 * n0, w1 = c1 * n1, w2 = c2 * n2, w3 = c3 * n3;
            s = fmaf(w0, w0, fmaf(w1, w1, fmaf(w2, w2, fmaf(w3, w3, s))));
            ws4[j * 256 + tid] = make_float4(w0, w1, w2, w3);  // private slot
        }

        // --- per-token norm: warp reduce + 4 warps per token via smem ---
#pragma unroll
        for (int off = 16; off > 0; off >>= 1)
            s += __shfl_xor_sync(0xffffffffu, s, off);
        if (l == 0) red[w] = s;
        __syncthreads();
        const float S = red[t * 4] + red[t * 4 + 1] + red[t * 4 + 2] + red[t * 4 + 3];
        const float inv = __fdividef(1.0f, sqrtf(S) + 1e-8f);

        // --- read own staged values, finalize |w| * inv, single store ---
        float* o = out + (size_t)tok * DTOT + dg;
#pragma unroll
        for (int j = 0; j < 8; j++) {
            float4 v = ws4[j * 256 + tid];
            const int qe = j * 8 + (l & 3) * 2;
            float* oj = o + qe * 64;
            __stcg(oj,      fabsf(v.x) * inv);
            __stcg(oj + 64, fabsf(v.y) * inv);
            __stcg(oj + 8,  fabsf(v.z) * inv);
            __stcg(oj + 72, fabsf(v.w) * inv);
        }
    }
}

// ------------------------- launch ------------------------------------------
extern "C" void kernel_launch(void* const* d_in, const int* in_sizes, int n_in,
                              void* d_out, int out_size)
{
    const float* x  = (const float*)d_in[0];
    const float* rx = (const float*)d_in[1];
    const float* ry = (const float*)d_in[2];
    const float* rz = (const float*)d_in[3];
    float* out = (float*)d_out;

    unsigned ka0, ka1;
    threefry2x32(0u, 42u, 0u, 0u, ka0, ka1);

    setup_kernel<<<1, 256>>>(rx, ry, rz);
    quantum_main<<<PGRID, 256>>>(x, out, ka0, ka1);
}

// round 12
// speedup vs baseline: 1.2861x; 1.0402x over previous
#include <cuda_runtime.h>
#include <cuda_bf16.h>
#include <cuda_fp16.h>
#include <cstdint>
#include <math.h>

// ---------------------------------------------------------------------------
// QuantumLayer: three FFT-diagonal rotations = ONE real 64x64 circulant along
// the qubit axis -> bf16-split mma.sync HMMA (tensor pipe). Amplitude noise
// (threefry2x32, JAX partitionable) + per-token L2 norm + abs, fused.
// R7 structure; dual HMMA accumulator chains; fp16 smem staging for the
// epilogue (no L2 round-trip).
// ---------------------------------------------------------------------------

#define DTOT 4096
#define CTAS 2048          // 2 tokens per CTA

// B-fragment table, fragment-register order: [img(hi,lo)][j(8)][kk(4)][lane(32)]
__device__ uint2 d_Bfrag[2048];

// ------------------------- small helpers -----------------------------------
__device__ __forceinline__ unsigned smem_u32(const void* p) {
    unsigned a;
    asm("{ .reg .u64 t; cvta.to.shared.u64 t, %1; cvt.u32.u64 %0, t; }" : "=r"(a) : "l"(p));
    return a;
}
__device__ __forceinline__ void cp_async16(void* s, const void* g) {
    asm volatile("cp.async.ca.shared.global [%0], [%1], 16;" :: "r"(smem_u32(s)), "l"(g));
}
// pack two f32 -> bf16x2, first arg in LOW half
__device__ __forceinline__ unsigned pack_bf16x2(float lo_e, float hi_e) {
    unsigned r;
    asm("cvt.rn.bf16x2.f32 %0, %1, %2;" : "=r"(r) : "f"(hi_e), "f"(lo_e));
    return r;
}
__device__ __forceinline__ unsigned pack_f16x2(float lo_e, float hi_e) {
    unsigned r;
    asm("cvt.rn.f16x2.f32 %0, %1, %2;" : "=r"(r) : "f"(hi_e), "f"(lo_e));
    return r;
}
__device__ __forceinline__ void split2(float a, float b, unsigned &hi, unsigned &lo) {
    unsigned h = pack_bf16x2(a, b);
    float ha = __uint_as_float(h << 16);
    float hb = __uint_as_float(h & 0xffff0000u);
    hi = h;
    lo = pack_bf16x2(a - ha, b - hb);
}
#define HMMA(c0,c1,c2,c3,a,b0,b1)                                              \
    asm volatile("mma.sync.aligned.m16n8k16.row.col.f32.bf16.bf16.f32 "        \
        "{%0,%1,%2,%3}, {%4,%5,%6,%7}, {%8,%9}, {%0,%1,%2,%3};"                \
        : "+f"(c0), "+f"(c1), "+f"(c2), "+f"(c3)                               \
        : "r"((a)[0]), "r"((a)[1]), "r"((a)[2]), "r"((a)[3]), "r"(b0), "r"(b1))

// ------------------------- threefry2x32 (exact) ----------------------------
__host__ __device__ __forceinline__ unsigned rotl32(unsigned x, int r) {
#if defined(__CUDA_ARCH__)
    return __funnelshift_l(x, x, r);
#else
    return (x << r) | (x >> (32 - r));
#endif
}
__host__ __device__ __forceinline__ void threefry2x32(
    unsigned k0, unsigned k1, unsigned c0, unsigned c1, unsigned &y0, unsigned &y1)
{
    unsigned ks2 = k0 ^ k1 ^ 0x1BD11BDAu;
    unsigned x0 = c0 + k0;
    unsigned x1 = c1 + k1;
#define TF_R(r) { x0 += x1; x1 = rotl32(x1, (r)); x1 ^= x0; }
    TF_R(13) TF_R(15) TF_R(26) TF_R(6)
    x0 += k1;  x1 += ks2 + 1u;
    TF_R(17) TF_R(29) TF_R(16) TF_R(24)
    x0 += ks2; x1 += k0 + 2u;
    TF_R(13) TF_R(15) TF_R(26) TF_R(6)
    x0 += k0;  x1 += k1 + 3u;
    TF_R(17) TF_R(29) TF_R(16) TF_R(24)
    x0 += k1;  x1 += ks2 + 4u;
    TF_R(13) TF_R(15) TF_R(26) TF_R(6)
    x0 += ks2; x1 += k0 + 5u;
#undef TF_R
    y0 = x0; y1 = x1;
}

__device__ __forceinline__ float erfinv_approx(float x)
{
    float w = -__logf(fmaf(-x, x, 1.0f));
    float p;
    if (w < 5.0f) {
        w = w - 2.5f;
        p = 2.81022636e-08f;
        p = fmaf(p, w, 3.43273939e-07f);
        p = fmaf(p, w, -3.5233877e-06f);
        p = fmaf(p, w, -4.39150654e-06f);
        p = fmaf(p, w, 0.00021858087f);
        p = fmaf(p, w, -0.00125372503f);
        p = fmaf(p, w, -0.00417768164f);
        p = fmaf(p, w, 0.246640727f);
        p = fmaf(p, w, 1.50140941f);
    } else {
        w = sqrtf(w) - 3.0f;
        p = -0.000200214257f;
        p = fmaf(p, w, 0.000100950558f);
        p = fmaf(p, w, 0.00134934322f);
        p = fmaf(p, w, -0.00367342844f);
        p = fmaf(p, w, 0.00573950773f);
        p = fmaf(p, w, -0.0076224613f);
        p = fmaf(p, w, 0.00943887047f);
        p = fmaf(p, w, 1.00167406f);
        p = fmaf(p, w, 2.83297682f);
    }
    return p * x;
}
__device__ __forceinline__ float noise_mult(
    unsigned k0, unsigned k1, unsigned ks2, unsigned j)
{
    unsigned x0 = k0;
    unsigned x1 = j + k1;
#define TF_R(r) { x0 += x1; x1 = rotl32(x1, (r)); x1 ^= x0; }
    TF_R(13) TF_R(15) TF_R(26) TF_R(6)
    x0 += k1;  x1 += ks2 + 1u;
    TF_R(17) TF_R(29) TF_R(16) TF_R(24)
    x0 += ks2; x1 += k0 + 2u;
    TF_R(13) TF_R(15) TF_R(26) TF_R(6)
    x0 += k0;  x1 += k1 + 3u;
    TF_R(17) TF_R(29) TF_R(16) TF_R(24)
    x0 += k1;  x1 += ks2 + 4u;
    TF_R(13) TF_R(15) TF_R(26) TF_R(6)
    x0 += ks2; x1 += k0 + 5u;
#undef TF_R
    unsigned bits = x0 ^ x1;
    float v = (float)(bits >> 9);                       // exact I2F (23 bits)
    float u = fmaf(v, 2.3841858e-07f, -0.99999994f);    // jax uniform mapping
    float z = 1.41421354f * erfinv_approx(u);
    return fmaf(z, 0.01f, 1.0f);
}

// ------------------------- setup: generator + B-fragment table -------------
__global__ void setup_kernel(const float* __restrict__ rx,
                             const float* __restrict__ ry,
                             const float* __restrict__ rz)
{
    __shared__ float c64[64], s64[64];
    __shared__ float cthx[32], cthy[32], cthz[32], sthz[32];
    __shared__ float cx[64], cy[64], cz[64], hh[64], gg[64];
    const int tid = threadIdx.x;   // 0..255
    const int m = tid;

    if (m < 64) {
        c64[m] = cospif((float)m / 32.0f);
        s64[m] = sinpif((float)m / 32.0f);
    }
    if (m < 32) {
        float sx = 0.0f, sy = 0.0f, sz = 0.0f;
        for (int j = 0; j < 16; j++) {
            sx += rx[m * 16 + j];
            sy += ry[m * 16 + j];
            sz += rz[m * 16 + j];
        }
        cthx[m] = cosf(0.5f * sx);
        cthy[m] = cosf(0.5f * sy);
        cthz[m] = cosf(0.5f * sz);
        sthz[m] = sinf(0.5f * sz);
    }
    __syncthreads();

    if (m < 64) {
        float ax = 0.0f, ay = 0.0f, az = 0.0f;
        for (int k = 0; k < 32; k++) {
            int n0 = (2 * k * m) & 63;
            int n1 = ((2 * k + 1) * m) & 63;
            float cc = c64[n0] + c64[n1];
            ax = fmaf(cthx[k], cc, ax);
            ay = fmaf(cthy[k], cc, ay);
            az = fmaf(cthz[k], cc, fmaf(sthz[k], s64[n0] - s64[n1], az));
        }
        cx[m] = ax * (1.0f / 64.0f);
        cy[m] = ay * (1.0f / 64.0f);
        cz[m] = az * (1.0f / 64.0f);
    }
    __syncthreads();

    if (m < 64) {
        float acc = 0.0f;
        for (int s = 0; s < 64; s++) acc = fmaf(cy[s], cx[(m - s) & 63], acc);
        hh[m] = acc;
    }
    __syncthreads();

    if (m < 64) {
        float g = 0.0f;
        for (int s = 0; s < 64; s++) g = fmaf(cz[s], hh[(m - s) & 63], g);
        gg[m] = g;
    }
    __syncthreads();

    // B = G^T fragments for mma.m16n8k16.row.col: B[k=p][n=q] = g[(q-p)&63]
    for (int e = tid; e < 2048; e += 256) {
        int lane = e & 31;
        int kk   = (e >> 5) & 3;
        int j    = (e >> 7) & 7;
        int img  = e >> 10;
        int p0 = kk * 16 + (lane & 3) * 2;
        int q  = j * 8 + (lane >> 2);
        float v0 = gg[(q - p0) & 63];
        float v1 = gg[(q - p0 - 1) & 63];
        float v2 = gg[(q - p0 - 8) & 63];
        float v3 = gg[(q - p0 - 9) & 63];
        unsigned h0, l0, h1, l1;
        split2(v0, v1, h0, l0);
        split2(v2, v3, h1, l1);
        d_Bfrag[e] = (img == 0) ? make_uint2(h0, h1) : make_uint2(l0, l1);
    }
}

// ------------------------- main kernel -------------------------------------
__global__ void __launch_bounds__(256, 4)
quantum_main(const float* __restrict__ x, float* __restrict__ out,
             unsigned ka0, unsigned ka1)
{
    __shared__ __align__(16) uint2 Bf[2048];    // [img][j][kk][lane], 16KB
    __shared__ __align__(16) uint2 wsh[2048];   // fp16x2 staging [j][tid], 16KB
    __shared__ float red[8];

    const int tid = threadIdx.x;
    const int w   = tid >> 5;
    const int l   = tid & 31;
    const int t   = w >> 2;                   // token within CTA pair
    const int dg  = (w & 3) * 16 + (l >> 2);  // this thread's base d (row)
    const int blk = blockIdx.x;
    const unsigned ks2 = ka0 ^ ka1 ^ 0x1BD11BDAu;

    // --- async copy of B fragments (64B per thread) ---
#pragma unroll
    for (int i = 0; i < 4; i++)
        cp_async16(&Bf[tid * 8 + i * 2], &d_Bfrag[tid * 8 + i * 2]);
    asm volatile("cp.async.commit_group;");

    // --- A fragments straight from gmem (each byte read once, 4-sector LDGs) ---
    const float* xb = x + (size_t)(2 * blk + t) * DTOT + dg;
    unsigned ahi[4][4], alo[4][4];
#pragma unroll
    for (int kk = 0; kk < 4; kk++) {
        const float* xp = xb + (kk * 16 + (l & 3) * 2) * 64;
        float v00 = xp[0],        v01 = xp[64];
        float v10 = xp[8],        v11 = xp[64 + 8];
        float v20 = xp[512],      v21 = xp[576];
        float v30 = xp[512 + 8],  v31 = xp[576 + 8];
        split2(v00, v01, ahi[kk][0], alo[kk][0]);
        split2(v10, v11, ahi[kk][1], alo[kk][1]);
        split2(v20, v21, ahi[kk][2], alo[kk][2]);
        split2(v30, v31, ahi[kk][3], alo[kk][3]);
    }

    asm volatile("cp.async.wait_group 0;");
    __syncthreads();

    // --- 8 n-tiles: 12 HMMAs as TWO independent 6-chains; noise; smem stage ---
    float s = 0.0f;
    const unsigned jb = (unsigned)((2 * blk + t) * DTOT) + (unsigned)dg;
#pragma unroll
    for (int j = 0; j < 8; j++) {
        float c0 = 0.f, c1 = 0.f, c2 = 0.f, c3 = 0.f;   // chain 1
        float d0 = 0.f, d1 = 0.f, d2 = 0.f, d3 = 0.f;   // chain 2
#pragma unroll
        for (int kk = 0; kk < 4; kk++) {
            uint2 bh = Bf[(j * 4 + kk) * 32 + l];
            uint2 bl = Bf[1024 + (j * 4 + kk) * 32 + l];
            HMMA(c0, c1, c2, c3, ahi[kk], bh.x, bh.y);
            HMMA(d0, d1, d2, d3, ahi[kk], bl.x, bl.y);
            if (kk < 2) { HMMA(c0, c1, c2, c3, alo[kk], bh.x, bh.y); }
            else        { HMMA(d0, d1, d2, d3, alo[kk], bh.x, bh.y); }
        }
        const unsigned qe = (unsigned)(j * 8 + (l & 3) * 2);
        float n0 = noise_mult(ka0, ka1, ks2, jb + qe * 64u);
        float n1 = noise_mult(ka0, ka1, ks2, jb + qe * 64u + 64u);
        float n2 = noise_mult(ka0, ka1, ks2, jb + qe * 64u + 8u);
        float n3 = noise_mult(ka0, ka1, ks2, jb + qe * 64u + 72u);
        float w0 = (c0 + d0) * n0;
        float w1 = (c1 + d1) * n1;
        float w2 = (c2 + d2) * n2;
        float w3 = (c3 + d3) * n3;
        s = fmaf(w0, w0, fmaf(w1, w1, fmaf(w2, w2, fmaf(w3, w3, s))));
        wsh[j * 256 + tid] = make_uint2(pack_f16x2(w0, w1), pack_f16x2(w2, w3));
    }

    // --- per-token norm: warp reduce + 4 warps per token via smem ---
#pragma unroll
    for (int off = 16; off > 0; off >>= 1)
        s += __shfl_xor_sync(0xffffffffu, s, off);
    if (l == 0) red[w] = s;
    __syncthreads();
    const float S = red[t * 4] + red[t * 4 + 1] + red[t * 4 + 2] + red[t * 4 + 3];
    const float inv = __fdividef(1.0f, sqrtf(S) + 1e-8f);

    // --- read own staged fp16 values, finalize |w| * inv, store once ---
    float* o = out + (size_t)(2 * blk + t) * DTOT + dg;
#pragma unroll
    for (int j = 0; j < 8; j++) {
        uint2 pv = wsh[j * 256 + tid];
        float2 f01 = __half22float2(*reinterpret_cast<const __half2*>(&pv.x));
        float2 f23 = __half22float2(*reinterpret_cast<const __half2*>(&pv.y));
        const int qe = j * 8 + (l & 3) * 2;
        float* oj = o + qe * 64;
        __stcg(oj,      fabsf(f01.x) * inv);
        __stcg(oj + 64, fabsf(f01.y) * inv);
        __stcg(oj + 8,  fabsf(f23.x) * inv);
        __stcg(oj + 72, fabsf(f23.y) * inv);
    }
}

// ------------------------- launch ------------------------------------------
extern "C" void kernel_launch(void* const* d_in, const int* in_sizes, int n_in,
                              void* d_out, int out_size)
{
    const float* x  = (const float*)d_in[0];
    const float* rx = (const float*)d_in[1];
    const float* ry = (const float*)d_in[2];
    const float* rz = (const float*)d_in[3];
    float* out = (float*)d_out;

    unsigned ka0, ka1;
    threefry2x32(0u, 42u, 0u, 0u, ka0, ka1);

    setup_kernel<<<1, 256>>>(rx, ry, rz);
    quantum_main<<<CTAS, 256>>>(x, out, ka0, ka1);
}

// round 13
// speedup vs baseline: 1.2927x; 1.0051x over previous
#include <cuda_runtime.h>
#include <cuda_bf16.h>
#include <cuda_fp16.h>
#include <cstdint>
#include <math.h>

// ---------------------------------------------------------------------------
// QuantumLayer: three FFT-diagonal rotations = ONE real 64x64 circulant along
// the qubit axis -> bf16-split mma.sync HMMA (tensor pipe). Amplitude noise
// (threefry2x32, JAX partitionable) + per-token L2 norm + abs, fused.
// PHASED: (1) raw X LDGs issued, (2) pure-PRNG phase computes all 32 noise
// deltas/thread into smem (hiding the X load latency), (3) bf16 split,
// (4) HMMA matmul + delta apply + fp16 smem staging, (5) norm + store.
// ---------------------------------------------------------------------------

#define DTOT 4096
#define CTAS 2048          // 2 tokens per CTA

// B-fragment table, fragment-register order: [img(hi,lo)][j(8)][kk(4)][lane(32)]
__device__ uint2 d_Bfrag[2048];

// ------------------------- small helpers -----------------------------------
__device__ __forceinline__ unsigned smem_u32(const void* p) {
    unsigned a;
    asm("{ .reg .u64 t; cvta.to.shared.u64 t, %1; cvt.u32.u64 %0, t; }" : "=r"(a) : "l"(p));
    return a;
}
__device__ __forceinline__ void cp_async16(void* s, const void* g) {
    asm volatile("cp.async.ca.shared.global [%0], [%1], 16;" :: "r"(smem_u32(s)), "l"(g));
}
// pack two f32 -> bf16x2, first arg in LOW half
__device__ __forceinline__ unsigned pack_bf16x2(float lo_e, float hi_e) {
    unsigned r;
    asm("cvt.rn.bf16x2.f32 %0, %1, %2;" : "=r"(r) : "f"(hi_e), "f"(lo_e));
    return r;
}
__device__ __forceinline__ unsigned pack_f16x2(float lo_e, float hi_e) {
    unsigned r;
    asm("cvt.rn.f16x2.f32 %0, %1, %2;" : "=r"(r) : "f"(hi_e), "f"(lo_e));
    return r;
}
__device__ __forceinline__ void split2(float a, float b, unsigned &hi, unsigned &lo) {
    unsigned h = pack_bf16x2(a, b);
    float ha = __uint_as_float(h << 16);
    float hb = __uint_as_float(h & 0xffff0000u);
    hi = h;
    lo = pack_bf16x2(a - ha, b - hb);
}
#define HMMA(c0,c1,c2,c3,a,b0,b1)                                              \
    asm volatile("mma.sync.aligned.m16n8k16.row.col.f32.bf16.bf16.f32 "        \
        "{%0,%1,%2,%3}, {%4,%5,%6,%7}, {%8,%9}, {%0,%1,%2,%3};"                \
        : "+f"(c0), "+f"(c1), "+f"(c2), "+f"(c3)                               \
        : "r"((a)[0]), "r"((a)[1]), "r"((a)[2]), "r"((a)[3]), "r"(b0), "r"(b1))

// ------------------------- threefry2x32 (exact) ----------------------------
__host__ __device__ __forceinline__ unsigned rotl32(unsigned x, int r) {
#if defined(__CUDA_ARCH__)
    return __funnelshift_l(x, x, r);
#else
    return (x << r) | (x >> (32 - r));
#endif
}
__host__ __device__ __forceinline__ void threefry2x32(
    unsigned k0, unsigned k1, unsigned c0, unsigned c1, unsigned &y0, unsigned &y1)
{
    unsigned ks2 = k0 ^ k1 ^ 0x1BD11BDAu;
    unsigned x0 = c0 + k0;
    unsigned x1 = c1 + k1;
#define TF_R(r) { x0 += x1; x1 = rotl32(x1, (r)); x1 ^= x0; }
    TF_R(13) TF_R(15) TF_R(26) TF_R(6)
    x0 += k1;  x1 += ks2 + 1u;
    TF_R(17) TF_R(29) TF_R(16) TF_R(24)
    x0 += ks2; x1 += k0 + 2u;
    TF_R(13) TF_R(15) TF_R(26) TF_R(6)
    x0 += k0;  x1 += k1 + 3u;
    TF_R(17) TF_R(29) TF_R(16) TF_R(24)
    x0 += k1;  x1 += ks2 + 4u;
    TF_R(13) TF_R(15) TF_R(26) TF_R(6)
    x0 += ks2; x1 += k0 + 5u;
#undef TF_R
    y0 = x0; y1 = x1;
}

__device__ __forceinline__ float erfinv_approx(float x)
{
    float w = -__logf(fmaf(-x, x, 1.0f));
    float p;
    if (w < 5.0f) {
        w = w - 2.5f;
        p = 2.81022636e-08f;
        p = fmaf(p, w, 3.43273939e-07f);
        p = fmaf(p, w, -3.5233877e-06f);
        p = fmaf(p, w, -4.39150654e-06f);
        p = fmaf(p, w, 0.00021858087f);
        p = fmaf(p, w, -0.00125372503f);
        p = fmaf(p, w, -0.00417768164f);
        p = fmaf(p, w, 0.246640727f);
        p = fmaf(p, w, 1.50140941f);
    } else {
        w = sqrtf(w) - 3.0f;
        p = -0.000200214257f;
        p = fmaf(p, w, 0.000100950558f);
        p = fmaf(p, w, 0.00134934322f);
        p = fmaf(p, w, -0.00367342844f);
        p = fmaf(p, w, 0.00573950773f);
        p = fmaf(p, w, -0.0076224613f);
        p = fmaf(p, w, 0.00943887047f);
        p = fmaf(p, w, 1.00167406f);
        p = fmaf(p, w, 2.83297682f);
    }
    return p * x;
}
// delta = 0.01 * z  (noise multiplier = 1 + delta)
__device__ __forceinline__ float noise_delta(
    unsigned k0, unsigned k1, unsigned ks2, unsigned j)
{
    unsigned x0 = k0;
    unsigned x1 = j + k1;
#define TF_R(r) { x0 += x1; x1 = rotl32(x1, (r)); x1 ^= x0; }
    TF_R(13) TF_R(15) TF_R(26) TF_R(6)
    x0 += k1;  x1 += ks2 + 1u;
    TF_R(17) TF_R(29) TF_R(16) TF_R(24)
    x0 += ks2; x1 += k0 + 2u;
    TF_R(13) TF_R(15) TF_R(26) TF_R(6)
    x0 += k0;  x1 += k1 + 3u;
    TF_R(17) TF_R(29) TF_R(16) TF_R(24)
    x0 += k1;  x1 += ks2 + 4u;
    TF_R(13) TF_R(15) TF_R(26) TF_R(6)
    x0 += ks2; x1 += k0 + 5u;
#undef TF_R
    unsigned bits = x0 ^ x1;
    float v = (float)(bits >> 9);                       // exact I2F (23 bits)
    float u = fmaf(v, 2.3841858e-07f, -0.99999994f);    // jax uniform mapping
    float z = 1.41421354f * erfinv_approx(u);
    return 0.01f * z;
}

// ------------------------- setup: generator + B-fragment table -------------
__global__ void setup_kernel(const float* __restrict__ rx,
                             const float* __restrict__ ry,
                             const float* __restrict__ rz)
{
    __shared__ float c64[64], s64[64];
    __shared__ float cthx[32], cthy[32], cthz[32], sthz[32];
    __shared__ float cx[64], cy[64], cz[64], hh[64], gg[64];
    const int tid = threadIdx.x;   // 0..255
    const int m = tid;

    if (m < 64) {
        c64[m] = cospif((float)m / 32.0f);
        s64[m] = sinpif((float)m / 32.0f);
    }
    if (m < 32) {
        float sx = 0.0f, sy = 0.0f, sz = 0.0f;
        for (int j = 0; j < 16; j++) {
            sx += rx[m * 16 + j];
            sy += ry[m * 16 + j];
            sz += rz[m * 16 + j];
        }
        cthx[m] = cosf(0.5f * sx);
        cthy[m] = cosf(0.5f * sy);
        cthz[m] = cosf(0.5f * sz);
        sthz[m] = sinf(0.5f * sz);
    }
    __syncthreads();

    if (m < 64) {
        float ax = 0.0f, ay = 0.0f, az = 0.0f;
        for (int k = 0; k < 32; k++) {
            int n0 = (2 * k * m) & 63;
            int n1 = ((2 * k + 1) * m) & 63;
            float cc = c64[n0] + c64[n1];
            ax = fmaf(cthx[k], cc, ax);
            ay = fmaf(cthy[k], cc, ay);
            az = fmaf(cthz[k], cc, fmaf(sthz[k], s64[n0] - s64[n1], az));
        }
        cx[m] = ax * (1.0f / 64.0f);
        cy[m] = ay * (1.0f / 64.0f);
        cz[m] = az * (1.0f / 64.0f);
    }
    __syncthreads();

    if (m < 64) {
        float acc = 0.0f;
        for (int s = 0; s < 64; s++) acc = fmaf(cy[s], cx[(m - s) & 63], acc);
        hh[m] = acc;
    }
    __syncthreads();

    if (m < 64) {
        float g = 0.0f;
        for (int s = 0; s < 64; s++) g = fmaf(cz[s], hh[(m - s) & 63], g);
        gg[m] = g;
    }
    __syncthreads();

    // B = G^T fragments for mma.m16n8k16.row.col: B[k=p][n=q] = g[(q-p)&63]
    for (int e = tid; e < 2048; e += 256) {
        int lane = e & 31;
        int kk   = (e >> 5) & 3;
        int j    = (e >> 7) & 7;
        int img  = e >> 10;
        int p0 = kk * 16 + (lane & 3) * 2;
        int q  = j * 8 + (lane >> 2);
        float v0 = gg[(q - p0) & 63];
        float v1 = gg[(q - p0 - 1) & 63];
        float v2 = gg[(q - p0 - 8) & 63];
        float v3 = gg[(q - p0 - 9) & 63];
        unsigned h0, l0, h1, l1;
        split2(v0, v1, h0, l0);
        split2(v2, v3, h1, l1);
        d_Bfrag[e] = (img == 0) ? make_uint2(h0, h1) : make_uint2(l0, l1);
    }
}

// ------------------------- main kernel -------------------------------------
__global__ void __launch_bounds__(256, 4)
quantum_main(const float* __restrict__ x, float* __restrict__ out,
             unsigned ka0, unsigned ka1)
{
    __shared__ __align__(16) uint2 Bf[2048];    // [img][j][kk][lane], 16KB
    __shared__ __align__(16) uint2 wsh[2048];   // fp16x2 staging [j][tid], 16KB
    __shared__ float red[8];

    const int tid = threadIdx.x;
    const int w   = tid >> 5;
    const int l   = tid & 31;
    const int t   = w >> 2;                   // token within CTA pair
    const int dg  = (w & 3) * 16 + (l >> 2);  // this thread's base d (row)
    const int blk = blockIdx.x;
    const unsigned ks2 = ka0 ^ ka1 ^ 0x1BD11BDAu;

    // --- phase 0: issue all loads ---
#pragma unroll
    for (int i = 0; i < 4; i++)
        cp_async16(&Bf[tid * 8 + i * 2], &d_Bfrag[tid * 8 + i * 2]);
    asm volatile("cp.async.commit_group;");

    const float* xb = x + (size_t)(2 * blk + t) * DTOT + dg;
    float xv[16];
#pragma unroll
    for (int kk = 0; kk < 4; kk++) {
        const float* xp = xb + (kk * 16 + (l & 3) * 2) * 64;
        xv[kk * 4 + 0] = xp[0];
        xv[kk * 4 + 1] = xp[64];
        xv[kk * 4 + 2] = xp[8];
        xv[kk * 4 + 3] = xp[64 + 8];
        // second k-octet loaded later (reuses xp, see split phase)
    }

    // --- phase 1: pure PRNG — 32 deltas into smem (hides X load latency) ---
    const unsigned jb = (unsigned)((2 * blk + t) * DTOT) + (unsigned)dg;
#pragma unroll
    for (int j = 0; j < 8; j++) {
        const unsigned b = jb + (unsigned)(j * 8 + (l & 3) * 2) * 64u;
        float d0 = noise_delta(ka0, ka1, ks2, b);
        float d1 = noise_delta(ka0, ka1, ks2, b + 64u);
        float d2 = noise_delta(ka0, ka1, ks2, b + 8u);
        float d3 = noise_delta(ka0, ka1, ks2, b + 72u);
        wsh[j * 256 + tid] = make_uint2(pack_f16x2(d0, d1), pack_f16x2(d2, d3));
    }

    // --- phase 2: bf16-split A fragments ---
    unsigned ahi[4][4], alo[4][4];
#pragma unroll
    for (int kk = 0; kk < 4; kk++) {
        const float* xp = xb + (kk * 16 + (l & 3) * 2) * 64;
        split2(xv[kk * 4 + 0], xv[kk * 4 + 1], ahi[kk][0], alo[kk][0]);
        split2(xv[kk * 4 + 2], xv[kk * 4 + 3], ahi[kk][1], alo[kk][1]);
        float v20 = xp[512], v21 = xp[576];
        float v30 = xp[512 + 8], v31 = xp[576 + 8];
        split2(v20, v21, ahi[kk][2], alo[kk][2]);
        split2(v30, v31, ahi[kk][3], alo[kk][3]);
    }

    asm volatile("cp.async.wait_group 0;");
    __syncthreads();

    // --- phase 3: 8 n-tiles, 12 HMMAs as two 6-chains; apply deltas ---
    float s = 0.0f;
#pragma unroll
    for (int j = 0; j < 8; j++) {
        float c0 = 0.f, c1 = 0.f, c2 = 0.f, c3 = 0.f;   // chain 1
        float d0 = 0.f, d1 = 0.f, d2 = 0.f, d3 = 0.f;   // chain 2
#pragma unroll
        for (int kk = 0; kk < 4; kk++) {
            uint2 bh = Bf[(j * 4 + kk) * 32 + l];
            uint2 bl = Bf[1024 + (j * 4 + kk) * 32 + l];
            HMMA(c0, c1, c2, c3, ahi[kk], bh.x, bh.y);
            HMMA(d0, d1, d2, d3, ahi[kk], bl.x, bl.y);
            if (kk < 2) { HMMA(c0, c1, c2, c3, alo[kk], bh.x, bh.y); }
            else        { HMMA(d0, d1, d2, d3, alo[kk], bh.x, bh.y); }
        }
        uint2 pv = wsh[j * 256 + tid];
        float2 n01 = __half22float2(*reinterpret_cast<const __half2*>(&pv.x));
        float2 n23 = __half22float2(*reinterpret_cast<const __half2*>(&pv.y));
        float y0 = c0 + d0, y1 = c1 + d1, y2 = c2 + d2, y3 = c3 + d3;
        float w0 = fmaf(y0, n01.x, y0);
        float w1 = fmaf(y1, n01.y, y1);
        float w2 = fmaf(y2, n23.x, y2);
        float w3 = fmaf(y3, n23.y, y3);
        s = fmaf(w0, w0, fmaf(w1, w1, fmaf(w2, w2, fmaf(w3, w3, s))));
        wsh[j * 256 + tid] = make_uint2(pack_f16x2(w0, w1), pack_f16x2(w2, w3));
    }

    // --- per-token norm: warp reduce + 4 warps per token via smem ---
#pragma unroll
    for (int off = 16; off > 0; off >>= 1)
        s += __shfl_xor_sync(0xffffffffu, s, off);
    if (l == 0) red[w] = s;
    __syncthreads();
    const float S = red[t * 4] + red[t * 4 + 1] + red[t * 4 + 2] + red[t * 4 + 3];
    const float inv = __fdividef(1.0f, sqrtf(S) + 1e-8f);

    // --- read own staged fp16 values, finalize |w| * inv, store once ---
    float* o = out + (size_t)(2 * blk + t) * DTOT + dg;
#pragma unroll
    for (int j = 0; j < 8; j++) {
        uint2 pv = wsh[j * 256 + tid];
        float2 f01 = __half22float2(*reinterpret_cast<const __half2*>(&pv.x));
        float2 f23 = __half22float2(*reinterpret_cast<const __half2*>(&pv.y));
        const int qe = j * 8 + (l & 3) * 2;
        float* oj = o + qe * 64;
        __stcg(oj,      fabsf(f01.x) * inv);
        __stcg(oj + 64, fabsf(f01.y) * inv);
        __stcg(oj + 8,  fabsf(f23.x) * inv);
        __stcg(oj + 72, fabsf(f23.y) * inv);
    }
}

// ------------------------- launch ------------------------------------------
extern "C" void kernel_launch(void* const* d_in, const int* in_sizes, int n_in,
                              void* d_out, int out_size)
{
    const float* x  = (const float*)d_in[0];
    const float* rx = (const float*)d_in[1];
    const float* ry = (const float*)d_in[2];
    const float* rz = (const float*)d_in[3];
    float* out = (float*)d_out;

    unsigned ka0, ka1;
    threefry2x32(0u, 42u, 0u, 0u, ka0, ka1);

    setup_kernel<<<1, 256>>>(rx, ry, rz);
    quantum_main<<<CTAS, 256>>>(x, out, ka0, ka1);
}